// round 1
// baseline (speedup 1.0000x reference)
#include <cuda_runtime.h>
#include <math.h>

// SymInfoNCELoss: B=4096, D=256, 4 views, TEMP=0.1, EPS=1e-8
// loss = (1/6) * sum_pairs [ 0.5*(mean_b LSE_row_b + mean_b LSE_col_b) - mean_b S_bb ]
// where S = (z_i_hat @ z_j_hat^T) / TEMP. sqrt(10) folded into each normalized vector.

#define BATCH 4096
#define DIM   256
#define NPAIR 6

#define BM 128
#define BN 128
#define BKK 16
#define TM 8
#define TN 8

// scratch (device globals: no allocations allowed)
__device__ float g_zn[4u * BATCH * DIM];          // normalized * sqrt(10)
__device__ float g_rowsum[NPAIR * BATCH];         // sum_j exp(S_ij)
__device__ float g_colsum[NPAIR * BATCH];         // sum_i exp(S_ij)
__device__ float g_diag[NPAIR];                   // sum_b S_bb

__constant__ int c_pi[NPAIR] = {0, 0, 0, 1, 1, 2};
__constant__ int c_pj[NPAIR] = {1, 2, 3, 2, 3, 3};

// ---------------------------------------------------------------------------
__global__ void zero_kernel() {
    int t = blockIdx.x * blockDim.x + threadIdx.x;
    if (t < NPAIR * BATCH) {
        g_rowsum[t] = 0.0f;
        g_colsum[t] = 0.0f;
    }
    if (t < NPAIR) g_diag[t] = 0.0f;
}

// one block (64 threads) per row; 4*4096 rows
__global__ void norm_kernel(const float* __restrict__ z0,
                            const float* __restrict__ z1,
                            const float* __restrict__ z2,
                            const float* __restrict__ z3) {
    int row = blockIdx.x;                 // 0..16383
    int v   = row >> 12;
    int r   = row & (BATCH - 1);
    const float* src = (v == 0) ? z0 : (v == 1) ? z1 : (v == 2) ? z2 : z3;

    const float4* p = reinterpret_cast<const float4*>(src + (size_t)r * DIM);
    float4 val = p[threadIdx.x];          // 64 threads * 4 = 256
    float ss = val.x * val.x + val.y * val.y + val.z * val.z + val.w * val.w;

    #pragma unroll
    for (int o = 16; o > 0; o >>= 1)
        ss += __shfl_xor_sync(0xffffffffu, ss, o);

    __shared__ float sw[2];
    if ((threadIdx.x & 31) == 0) sw[threadIdx.x >> 5] = ss;
    __syncthreads();
    float tot = sw[0] + sw[1];

    // sqrt(10)/max(||z||, 1e-8): folds 1/TEMP into the dot product
    float inv = 3.1622776601683795f / fmaxf(sqrtf(tot), 1e-8f);

    float4 o4 = make_float4(val.x * inv, val.y * inv, val.z * inv, val.w * inv);
    reinterpret_cast<float4*>(&g_zn[(size_t)row * DIM])[threadIdx.x] = o4;
}

// ---------------------------------------------------------------------------
// One 128x128 tile of S per block; fused exp + row/col sums + diagonal.
__global__ void __launch_bounds__(256)
pair_kernel() {
    __shared__ float As[BKK][BM + 4];
    __shared__ float Bs[BKK][BN + 4];
    __shared__ float sc[BN];

    const int pair = blockIdx.z;
    const int row0 = blockIdx.y * BM;
    const int col0 = blockIdx.x * BN;

    const float* __restrict__ A = g_zn + ((size_t)c_pi[pair] * BATCH + row0) * DIM;
    const float* __restrict__ Bp = g_zn + ((size_t)c_pj[pair] * BATCH + col0) * DIM;

    const int tid = threadIdx.x;
    const int ty  = tid >> 4;     // 0..15
    const int tx  = tid & 15;     // 0..15

    float acc[TM][TN];
    #pragma unroll
    for (int i = 0; i < TM; i++)
        #pragma unroll
        for (int j = 0; j < TN; j++) acc[i][j] = 0.0f;

    for (int k0 = 0; k0 < DIM; k0 += BKK) {
        // load 128x16 of A and B (as float4), store k-major into shared
        #pragma unroll
        for (int q = 0; q < 2; q++) {
            int idx = tid + q * 256;        // 0..511
            int m   = idx >> 2;             // 0..127
            int kq  = idx & 3;              // which float4 along k
            float4 va = *reinterpret_cast<const float4*>(A + (size_t)m * DIM + k0 + kq * 4);
            As[kq * 4 + 0][m] = va.x;
            As[kq * 4 + 1][m] = va.y;
            As[kq * 4 + 2][m] = va.z;
            As[kq * 4 + 3][m] = va.w;
            float4 vb = *reinterpret_cast<const float4*>(Bp + (size_t)m * DIM + k0 + kq * 4);
            Bs[kq * 4 + 0][m] = vb.x;
            Bs[kq * 4 + 1][m] = vb.y;
            Bs[kq * 4 + 2][m] = vb.z;
            Bs[kq * 4 + 3][m] = vb.w;
        }
        __syncthreads();

        #pragma unroll
        for (int kk = 0; kk < BKK; kk++) {
            float4 a0 = *reinterpret_cast<const float4*>(&As[kk][ty * TM]);
            float4 a1 = *reinterpret_cast<const float4*>(&As[kk][ty * TM + 4]);
            float4 b0 = *reinterpret_cast<const float4*>(&Bs[kk][tx * TN]);
            float4 b1 = *reinterpret_cast<const float4*>(&Bs[kk][tx * TN + 4]);
            float a[TM] = {a0.x, a0.y, a0.z, a0.w, a1.x, a1.y, a1.z, a1.w};
            float b[TN] = {b0.x, b0.y, b0.z, b0.w, b1.x, b1.y, b1.z, b1.w};
            #pragma unroll
            for (int i = 0; i < TM; i++)
                #pragma unroll
                for (int j = 0; j < TN; j++)
                    acc[i][j] += a[i] * b[j];
        }
        __syncthreads();
    }

    // ---- epilogue: S values are acc (sqrt10 folded into both operands) ----
    if (tid < BN) sc[tid] = 0.0f;
    __syncthreads();

    float rowp[TM];
    float colp[TN];
    #pragma unroll
    for (int i = 0; i < TM; i++) rowp[i] = 0.0f;
    #pragma unroll
    for (int j = 0; j < TN; j++) colp[j] = 0.0f;

    #pragma unroll
    for (int i = 0; i < TM; i++) {
        #pragma unroll
        for (int j = 0; j < TN; j++) {
            float ev = __expf(acc[i][j]);   // |S| <= 10, no overflow
            rowp[i] += ev;
            colp[j] += ev;
        }
    }

    // row partials: reduce across tx (16 lanes of the same half-warp)
    #pragma unroll
    for (int i = 0; i < TM; i++) {
        float r = rowp[i];
        #pragma unroll
        for (int o = 1; o < 16; o <<= 1)
            r += __shfl_xor_sync(0xffffffffu, r, o);
        if (tx == 0)
            atomicAdd(&g_rowsum[pair * BATCH + row0 + ty * TM + i], r);
    }

    // col partials: reduce across ty via shared atomics
    #pragma unroll
    for (int j = 0; j < TN; j++)
        atomicAdd(&sc[tx * TN + j], colp[j]);
    __syncthreads();
    if (tid < BN)
        atomicAdd(&g_colsum[pair * BATCH + col0 + tid], sc[tid]);

    // diagonal logits (only diagonal tile blocks contribute)
    if (blockIdx.x == blockIdx.y && ty == tx) {
        float d = 0.0f;
        #pragma unroll
        for (int i = 0; i < TM; i++) d += acc[i][i];
        atomicAdd(&g_diag[pair], d);
    }
}

// ---------------------------------------------------------------------------
__global__ void finalize_kernel(float* __restrict__ out) {
    __shared__ float red[256];
    float s = 0.0f;
    for (int i = threadIdx.x; i < NPAIR * BATCH; i += 256)
        s += logf(g_rowsum[i]) + logf(g_colsum[i]);
    red[threadIdx.x] = s;
    __syncthreads();
    for (int o = 128; o > 0; o >>= 1) {
        if (threadIdx.x < o) red[threadIdx.x] += red[threadIdx.x + o];
        __syncthreads();
    }
    if (threadIdx.x == 0) {
        float dsum = 0.0f;
        #pragma unroll
        for (int p = 0; p < NPAIR; p++) dsum += g_diag[p];
        out[0] = (0.5f * red[0] - dsum) / (6.0f * (float)BATCH);
    }
}

// ---------------------------------------------------------------------------
extern "C" void kernel_launch(void* const* d_in, const int* in_sizes, int n_in,
                              void* d_out, int out_size) {
    const float* z0 = (const float*)d_in[0];
    const float* z1 = (const float*)d_in[1];
    const float* z2 = (const float*)d_in[2];
    const float* z3 = (const float*)d_in[3];
    float* out = (float*)d_out;

    zero_kernel<<<(NPAIR * BATCH + 255) / 256, 256>>>();
    norm_kernel<<<4 * BATCH, 64>>>(z0, z1, z2, z3);
    dim3 grid(BATCH / BN, BATCH / BM, NPAIR);
    pair_kernel<<<grid, 256>>>();
    finalize_kernel<<<1, 256>>>(out);
}

// round 14
// speedup vs baseline: 8.4835x; 8.4835x over previous
#include <cuda_runtime.h>
#include <cuda_bf16.h>
#include <math.h>
#include <cstdint>

// SymInfoNCELoss via warp-level mma.sync (HMMA, base-PTX — tcgen05 is rejected
// by this harness's sm_103 PTX target).
// S = (zi_hat . zj_hat)/TEMP with sqrt(10) folded into each bf16 operand.
// loss = (1/(6B)) * [ 0.5*sum(log rowsum + log colsum) - sum diag ]

#define BATCH 4096
#define DIM   256
#define NPAIR 6
#define MT 128
#define NT 128
#define LDAB 264   // DIM + 8 bf16 pad: 528B row stride -> conflict-free ldmatrix

__device__ __align__(256) __nv_bfloat16 g_zn[4u * BATCH * DIM];
__device__ float g_rowsum[NPAIR * BATCH];
__device__ float g_colsum[NPAIR * BATCH];
__device__ float g_diag[NPAIR];

__constant__ int c_pi[NPAIR] = {0, 0, 0, 1, 1, 2};
__constant__ int c_pj[NPAIR] = {1, 2, 3, 2, 3, 3};

#define SMEM_TILE_BYTES (MT * LDAB * 2)          // 67584
#define SMEM_DYN        (2 * SMEM_TILE_BYTES)    // 135168

// ------------------------------------------------------------------ helpers
__device__ __forceinline__ uint32_t smem_u32(const void* p) {
    uint32_t a;
    asm("{ .reg .u64 t; cvta.to.shared.u64 t, %1; cvt.u32.u64 %0, t; }" : "=r"(a) : "l"(p));
    return a;
}
__device__ __forceinline__ void ldsm_x4(uint32_t r[4], uint32_t addr) {
    asm volatile("ldmatrix.sync.aligned.m8n8.x4.shared.b16 {%0,%1,%2,%3}, [%4];"
        : "=r"(r[0]), "=r"(r[1]), "=r"(r[2]), "=r"(r[3]) : "r"(addr));
}
__device__ __forceinline__ void ldsm_x2(uint32_t r[2], uint32_t addr) {
    asm volatile("ldmatrix.sync.aligned.m8n8.x2.shared.b16 {%0,%1}, [%2];"
        : "=r"(r[0]), "=r"(r[1]) : "r"(addr));
}
__device__ __forceinline__ void mma16816(float c[4], const uint32_t a[4], const uint32_t b[2]) {
    asm volatile("mma.sync.aligned.m16n8k16.row.col.f32.bf16.bf16.f32 "
        "{%0,%1,%2,%3}, {%4,%5,%6,%7}, {%8,%9}, {%0,%1,%2,%3};"
        : "+f"(c[0]), "+f"(c[1]), "+f"(c[2]), "+f"(c[3])
        : "r"(a[0]), "r"(a[1]), "r"(a[2]), "r"(a[3]), "r"(b[0]), "r"(b[1]));
}

// ------------------------------------------------------------------ kernels
__global__ void zero_kernel() {
    int t = blockIdx.x * blockDim.x + threadIdx.x;
    if (t < NPAIR * BATCH) { g_rowsum[t] = 0.0f; g_colsum[t] = 0.0f; }
    if (t < NPAIR) g_diag[t] = 0.0f;
}

// one 64-thread block per row (4*4096 rows); output bf16 * sqrt(10)/||z||
__global__ void norm_kernel(const float* __restrict__ z0, const float* __restrict__ z1,
                            const float* __restrict__ z2, const float* __restrict__ z3) {
    int row = blockIdx.x;
    int v = row >> 12, r = row & (BATCH - 1);
    const float* src = (v == 0) ? z0 : (v == 1) ? z1 : (v == 2) ? z2 : z3;

    float4 val = reinterpret_cast<const float4*>(src + (size_t)r * DIM)[threadIdx.x];
    float ss = val.x * val.x + val.y * val.y + val.z * val.z + val.w * val.w;
    #pragma unroll
    for (int o = 16; o > 0; o >>= 1) ss += __shfl_xor_sync(0xffffffffu, ss, o);

    __shared__ float sw[2];
    if ((threadIdx.x & 31) == 0) sw[threadIdx.x >> 5] = ss;
    __syncthreads();
    float inv = 3.1622776601683795f / fmaxf(sqrtf(sw[0] + sw[1]), 1e-8f);

    __nv_bfloat162 h0 = __floats2bfloat162_rn(val.x * inv, val.y * inv);
    __nv_bfloat162 h1 = __floats2bfloat162_rn(val.z * inv, val.w * inv);
    uint2 o4 = make_uint2(*reinterpret_cast<uint32_t*>(&h0), *reinterpret_cast<uint32_t*>(&h1));
    reinterpret_cast<uint2*>(&g_zn[(size_t)row * DIM])[threadIdx.x] = o4;
}

// One 128x128 tile of S per CTA; 8 warps (2 row x 4 col), warp tile 64x32.
// Fused exp + row/col/diag epilogue on register-resident accumulators.
__global__ void __launch_bounds__(256, 1)
pair_kernel() {
    extern __shared__ __align__(16) char dsm[];
    __nv_bfloat16* sA = reinterpret_cast<__nv_bfloat16*>(dsm);
    __nv_bfloat16* sB = reinterpret_cast<__nv_bfloat16*>(dsm + SMEM_TILE_BYTES);

    const int pair = blockIdx.z;
    const int row0 = blockIdx.y * MT;
    const int col0 = blockIdx.x * NT;
    const int tid = threadIdx.x;

    const __nv_bfloat16* Ag = g_zn + ((size_t)(c_pi[pair] * BATCH + row0)) * DIM;
    const __nv_bfloat16* Bg = g_zn + ((size_t)(c_pj[pair] * BATCH + col0)) * DIM;

    // ---- load A,B tiles (128 x 256 bf16 each) into padded smem ----------
    #pragma unroll
    for (int i = 0; i < 16; i++) {
        int idx = i * 256 + tid;          // 0..4095
        int r = idx >> 5;                 // 0..127
        int c = idx & 31;                 // 16B chunk along K
        *reinterpret_cast<uint4*>(sA + r * LDAB + c * 8) =
            *reinterpret_cast<const uint4*>(Ag + r * DIM + c * 8);
        *reinterpret_cast<uint4*>(sB + r * LDAB + c * 8) =
            *reinterpret_cast<const uint4*>(Bg + r * DIM + c * 8);
    }
    __syncthreads();

    const int w = tid >> 5, lane = tid & 31;
    const int wm = w & 1, wn = w >> 1;
    const int wr = wm * 64, wc = wn * 32;

    float acc[4][4][4];
    #pragma unroll
    for (int mt = 0; mt < 4; mt++)
        #pragma unroll
        for (int nt = 0; nt < 4; nt++)
            #pragma unroll
            for (int e = 0; e < 4; e++) acc[mt][nt][e] = 0.0f;

    // ldmatrix base addresses (bytes)
    const uint32_t aBase = smem_u32(sA + (wr + (lane & 15)) * LDAB + (lane >> 4) * 8);
    const uint32_t bBase = smem_u32(sB + (wc + (lane & 7)) * LDAB + ((lane >> 3) & 1) * 8);

    #pragma unroll
    for (int k0 = 0; k0 < DIM; k0 += 16) {
        uint32_t af[4][4], bf[4][2];
        #pragma unroll
        for (int mt = 0; mt < 4; mt++)
            ldsm_x4(af[mt], aBase + (uint32_t)(mt * 16 * LDAB + k0) * 2);
        #pragma unroll
        for (int nt = 0; nt < 4; nt++)
            ldsm_x2(bf[nt], bBase + (uint32_t)(nt * 8 * LDAB + k0) * 2);
        #pragma unroll
        for (int mt = 0; mt < 4; mt++)
            #pragma unroll
            for (int nt = 0; nt < 4; nt++)
                mma16816(acc[mt][nt], af[mt], bf[nt]);
    }

    // ---- epilogue ------------------------------------------------------
    // c0: (row g,   col 2q), c1: (g, 2q+1), c2: (g+8, 2q), c3: (g+8, 2q+1)
    // with g = lane>>2, q = lane&3
    const int g = lane >> 2, q = lane & 3;
    const bool diagTile = (row0 == col0);
    float colacc[4][2];
    #pragma unroll
    for (int nt = 0; nt < 4; nt++) { colacc[nt][0] = 0.0f; colacc[nt][1] = 0.0f; }
    float diagacc = 0.0f;

    #pragma unroll
    for (int mt = 0; mt < 4; mt++) {
        const int rlo = wr + mt * 16 + g;          // tile-local rows
        const int rhi = rlo + 8;
        float slo = 0.0f, shi = 0.0f;
        #pragma unroll
        for (int nt = 0; nt < 4; nt++) {
            const int cbase = wc + nt * 8 + q * 2; // tile-local col of c0/c2
            if (diagTile) {
                if (rlo == cbase)     diagacc += acc[mt][nt][0];
                if (rlo == cbase + 1) diagacc += acc[mt][nt][1];
                if (rhi == cbase)     diagacc += acc[mt][nt][2];
                if (rhi == cbase + 1) diagacc += acc[mt][nt][3];
            }
            float e0 = __expf(acc[mt][nt][0]);
            float e1 = __expf(acc[mt][nt][1]);
            float e2 = __expf(acc[mt][nt][2]);
            float e3 = __expf(acc[mt][nt][3]);
            slo += e0 + e1;
            shi += e2 + e3;
            colacc[nt][0] += e0 + e2;
            colacc[nt][1] += e1 + e3;
        }
        // reduce row sums across the 4 lanes sharing the same row (xor 1,2)
        #pragma unroll
        for (int o = 1; o <= 2; o <<= 1) {
            slo += __shfl_xor_sync(0xffffffffu, slo, o);
            shi += __shfl_xor_sync(0xffffffffu, shi, o);
        }
        if (q == 0) {
            atomicAdd(&g_rowsum[pair * BATCH + row0 + rlo], slo);
            atomicAdd(&g_rowsum[pair * BATCH + row0 + rhi], shi);
        }
    }

    // reduce col sums across the 8 lanes sharing the same col (xor 4,8,16)
    #pragma unroll
    for (int nt = 0; nt < 4; nt++) {
        #pragma unroll
        for (int o = 4; o <= 16; o <<= 1) {
            colacc[nt][0] += __shfl_xor_sync(0xffffffffu, colacc[nt][0], o);
            colacc[nt][1] += __shfl_xor_sync(0xffffffffu, colacc[nt][1], o);
        }
        if (g == 0) {
            const int cbase = wc + nt * 8 + q * 2;
            atomicAdd(&g_colsum[pair * BATCH + col0 + cbase],     colacc[nt][0]);
            atomicAdd(&g_colsum[pair * BATCH + col0 + cbase + 1], colacc[nt][1]);
        }
    }

    if (diagTile) {
        #pragma unroll
        for (int o = 16; o > 0; o >>= 1)
            diagacc += __shfl_xor_sync(0xffffffffu, diagacc, o);
        if (lane == 0) atomicAdd(&g_diag[pair], diagacc);
    }
}

__global__ void finalize_kernel(float* __restrict__ out) {
    __shared__ float red[1024];
    float s = 0.0f;
    for (int i = threadIdx.x; i < NPAIR * BATCH; i += 1024)
        s += __logf(g_rowsum[i]) + __logf(g_colsum[i]);
    red[threadIdx.x] = s;
    __syncthreads();
    for (int o = 512; o > 0; o >>= 1) {
        if (threadIdx.x < o) red[threadIdx.x] += red[threadIdx.x + o];
        __syncthreads();
    }
    if (threadIdx.x == 0) {
        float dsum = 0.0f;
        #pragma unroll
        for (int p = 0; p < NPAIR; p++) dsum += g_diag[p];
        out[0] = (0.5f * red[0] - dsum) / (6.0f * (float)BATCH);
    }
}

// ------------------------------------------------------------------ launch
extern "C" void kernel_launch(void* const* d_in, const int* in_sizes, int n_in,
                              void* d_out, int out_size) {
    const float* z0 = (const float*)d_in[0];
    const float* z1 = (const float*)d_in[1];
    const float* z2 = (const float*)d_in[2];
    const float* z3 = (const float*)d_in[3];
    float* out = (float*)d_out;

    cudaFuncSetAttribute(pair_kernel, cudaFuncAttributeMaxDynamicSharedMemorySize, SMEM_DYN);

    zero_kernel<<<(NPAIR * BATCH + 255) / 256, 256>>>();
    norm_kernel<<<4 * BATCH, 64>>>(z0, z1, z2, z3);
    dim3 grid(BATCH / NT, BATCH / MT, NPAIR);
    pair_kernel<<<grid, 256, SMEM_DYN>>>();
    finalize_kernel<<<1, 1024>>>(out);
}